// round 8
// baseline (speedup 1.0000x reference)
#include <cuda_runtime.h>
#include <cuda_bf16.h>
#include <math.h>

#define KE       14.3996f
#define ALPHA    0.3f
#define CUTOFF   10.0f
#define NMOL     64
#define MAXA     100000
#define MAXK     1024
#define TWOPI    6.283185307179586f
#define SQA      0.5477225575051661f   /* sqrt(0.3) */

#define RB   888          /* real-space blocks (148 SMs x 6) */
#define RTH  128          /* real-space threads per block    */
#define ASTR 65           /* acc row stride (words) -> bank (tid+mol)&31 */
#define NSLC 32           /* g_mid slices */

// -------- device scratch (no allocation allowed) --------
__device__ float  g_recip[NMOL][9];     // B[d][e] row-major: kv_e = sum_d g_d * B[d*3+e]
__device__ float  g_pref[NMOL];         // 2*pi / |det(cell)|
__device__ int    g_start[NMOL + 1];    // atom range per molecule (idx_m sorted)
__device__ int    g_halfk[MAXK];        // indices of half-space k vectors (any order)
__device__ int    g_nhalf;
__device__ float2 g_qmol[MAXA];         // {q, __int_as_float(mol)}
__device__ float  g_mid[NSLC * NMOL];   // sliced real-space partials

// =====================================================================
// Setup: zero out + g_mid, per-molecule recip boxes, molecule offsets
// (parallel boundary detection), half-k list (parallel compaction),
// packed (q, mol) array.  Indices are int32.
// =====================================================================
__global__ __launch_bounds__(256) void setup_kernel(
    const float* __restrict__ q, const float* __restrict__ cell,
    const float* __restrict__ kvecs, const int* __restrict__ idx_m,
    int natoms, int nk, float* __restrict__ out)
{
    int tid = threadIdx.x;
    if (blockIdx.x == 0) {
        __shared__ int cnt;
        if (tid == 0) cnt = 0;
        // zero sliced partials
        for (int i = tid; i < NSLC * NMOL; i += 256) g_mid[i] = 0.0f;
        if (tid < NMOL) {
            // 3x3 inverse for cell m = tid
            const float* a = cell + 9 * tid;
            float a00 = a[0], a01 = a[1], a02 = a[2];
            float a10 = a[3], a11 = a[4], a12 = a[5];
            float a20 = a[6], a21 = a[7], a22 = a[8];
            float c00 = a11 * a22 - a12 * a21;
            float c01 = a02 * a21 - a01 * a22;
            float c02 = a01 * a12 - a02 * a11;
            float c10 = a12 * a20 - a10 * a22;
            float c11 = a00 * a22 - a02 * a20;
            float c12 = a02 * a10 - a00 * a12;
            float c20 = a10 * a21 - a11 * a20;
            float c21 = a01 * a20 - a00 * a21;
            float c22 = a00 * a11 - a01 * a10;
            float det = a00 * c00 + a01 * c10 + a02 * c20;
            float id = 1.0f / det;
            float i00 = c00 * id, i01 = c01 * id, i02 = c02 * id;
            float i10 = c10 * id, i11 = c11 * id, i12 = c12 * id;
            float i20 = c20 * id, i21 = c21 * id, i22 = c22 * id;
            // B[d*3+e] = 2*pi * inv[e][d]  (recip_box = 2*pi * inv(cell)^T)
            g_recip[tid][0] = TWOPI * i00;
            g_recip[tid][1] = TWOPI * i10;
            g_recip[tid][2] = TWOPI * i20;
            g_recip[tid][3] = TWOPI * i01;
            g_recip[tid][4] = TWOPI * i11;
            g_recip[tid][5] = TWOPI * i21;
            g_recip[tid][6] = TWOPI * i02;
            g_recip[tid][7] = TWOPI * i12;
            g_recip[tid][8] = TWOPI * i22;
            g_pref[tid] = TWOPI / fabsf(det);
            out[tid] = 0.0f;
        }
        __syncthreads();
        // parallel half-space k compaction (sign-symmetric set: one of {k,-k})
        for (int k = tid; k < nk; k += 256) {
            float gx = kvecs[3 * k], gy = kvecs[3 * k + 1], gz = kvecs[3 * k + 2];
            bool sel = (gz > 0.0f) ||
                       (gz == 0.0f && gy > 0.0f) ||
                       (gz == 0.0f && gy == 0.0f && gx > 0.0f);
            if (sel) {
                int p = atomicAdd(&cnt, 1);
                if (p < MAXK) g_halfk[p] = k;
            }
        }
        __syncthreads();
        if (tid == 0) g_nhalf = min(cnt, MAXK);
    }
    // pack (q, mol) + parallel g_start boundary detection (idx_m sorted)
    for (int a = blockIdx.x * blockDim.x + tid; a < natoms; a += gridDim.x * blockDim.x) {
        int m = idx_m[a];
        g_qmol[a] = make_float2(q[a], __int_as_float(m));
        int mn = (a + 1 < natoms) ? idx_m[a + 1] : NMOL;
        for (int mm = m + 1; mm <= mn; mm++) g_start[mm] = a + 1;
        if (a == 0)
            for (int mm = 0; mm <= m; mm++) g_start[mm] = 0;
    }
}

// =====================================================================
// Real space: 4 pairs/thread via float4/int4 streaming loads; per-thread
// private shared accumulator rows (no atomics in the hot loop); block
// reduction into 32-sliced global partials.
// =====================================================================
__device__ __forceinline__ void do_pair(
    float x, float y, float z, int i, int j,
    const float* __restrict__ q, float* __restrict__ row,
    float frcut, float cut2)
{
    float d2 = fmaf(x, x, fmaf(y, y, z * z));
    if (d2 <= cut2) {
        float2 qm = __ldg(&g_qmol[i]);     // {q_i, mol bits} one 8B gather
        float qj = __ldg(&q[j]);
        float d = sqrtf(d2);
        float fr = __fdividef(erfcf(SQA * d), d) - frcut;
        row[__float_as_int(qm.y)] += qm.x * qj * fr;   // LDS+FFMA+STS, race-free
    }
}

__global__ __launch_bounds__(RTH) void real_kernel(
    const float* __restrict__ Rij,
    const int* __restrict__ idx_i, const int* __restrict__ idx_j,
    const float* __restrict__ q, int npairs)
{
    __shared__ float acc[RTH * ASTR];
    int tid = threadIdx.x;
    float* row = acc + tid * ASTR;
    #pragma unroll
    for (int m = 0; m < NMOL; m++) row[m] = 0.0f;

    const float frcut = erfcf(SQA * CUTOFF) / CUTOFF;
    const float cut2 = CUTOFF * CUTOFF;

    int nquad = npairs >> 2;
    const float4* r4 = (const float4*)Rij;
    const int4*   i4 = (const int4*)idx_i;
    const int4*   j4 = (const int4*)idx_j;

    for (int qd = blockIdx.x * RTH + tid; qd < nquad; qd += RB * RTH) {
        float4 A = r4[3 * qd], B = r4[3 * qd + 1], C = r4[3 * qd + 2];
        int4 ii = i4[qd];
        int4 jj = j4[qd];
        do_pair(A.x, A.y, A.z, ii.x, jj.x, q, row, frcut, cut2);
        do_pair(A.w, B.x, B.y, ii.y, jj.y, q, row, frcut, cut2);
        do_pair(B.z, B.w, C.x, ii.z, jj.z, q, row, frcut, cut2);
        do_pair(C.y, C.z, C.w, ii.w, jj.w, q, row, frcut, cut2);
    }
    // remainder pairs (npairs not divisible by 4)
    int rem = npairs - (nquad << 2);
    if (blockIdx.x == 0 && tid < rem) {
        int p = (nquad << 2) + tid;
        do_pair(Rij[3 * p], Rij[3 * p + 1], Rij[3 * p + 2],
                idx_i[p], idx_j[p], q, row, frcut, cut2);
    }

    __syncthreads();
    // block reduction: thread m (<64) sums its molecule over all rows.
    // addresses r*65+m -> bank (r+m)&31: conflict-free across the 2 warps.
    if (tid < NMOL) {
        float s = 0.0f;
        #pragma unroll 8
        for (int r = 0; r < RTH; r++) s += acc[r * ASTR + tid];
        atomicAdd(&g_mid[(blockIdx.x & (NSLC - 1)) * NMOL + tid], s);
    }
}

__global__ void fold_kernel(float* __restrict__ out)
{
    int m = threadIdx.x;
    if (m < NMOL) {
        float s = 0.0f;
        #pragma unroll
        for (int sl = 0; sl < NSLC; sl++) s += g_mid[sl * NMOL + m];
        atomicAdd(&out[m], 0.5f * KE * s);
    }
}

// =====================================================================
// Reciprocal space: block = (molecule, k-chunk), thread = one half-space k,
// loop over the molecule's atoms via shared float4 tiles. +- k symmetry => x2.
// Self-energy folded into blockIdx.y == 0 blocks.
// =====================================================================
#define RT 256

__device__ __forceinline__ float block_sum(float v, float* sh)
{
    #pragma unroll
    for (int o = 16; o; o >>= 1) v += __shfl_down_sync(0xffffffffu, v, o);
    int wid = threadIdx.x >> 5, lid = threadIdx.x & 31;
    if (lid == 0) sh[wid] = v;
    __syncthreads();
    if (wid == 0) {
        v = (lid < (RT >> 5)) ? sh[lid] : 0.0f;
        #pragma unroll
        for (int o = 4; o; o >>= 1) v += __shfl_down_sync(0xffffffffu, v, o);
    }
    return v;   // valid on thread 0
}

__global__ __launch_bounds__(RT) void recip_kernel(
    const float* __restrict__ R, const float* __restrict__ q,
    const float* __restrict__ kvecs, float* __restrict__ out)
{
    int m = blockIdx.x;
    int tid = threadIdx.x;
    int hk = blockIdx.y * RT + tid;

    float kvx = 0.f, kvy = 0.f, kvz = 0.f, w = 0.f;
    if (hk < g_nhalf) {
        int k = g_halfk[hk];
        float gx = kvecs[3 * k], gy = kvecs[3 * k + 1], gz = kvecs[3 * k + 2];
        const float* B = g_recip[m];
        kvx = gx * B[0] + gy * B[3] + gz * B[6];
        kvy = gx * B[1] + gy * B[4] + gz * B[7];
        kvz = gx * B[2] + gy * B[5] + gz * B[8];
        float ksq = kvx * kvx + kvy * kvy + kvz * kvz;
        w = 2.0f * expf(-0.25f * ksq / ALPHA) / ksq;   // x2: +-k symmetry
    }

    int s0 = g_start[m], s1 = g_start[m + 1];
    __shared__ float4 tile[RT];
    __shared__ float red[RT >> 5];

    float cr = 0.f, ci = 0.f, qq = 0.f;
    for (int base = s0; base < s1; base += RT) {
        int a = base + tid;
        if (a < s1) {
            float qa = q[a];
            tile[tid] = make_float4(R[3 * a], R[3 * a + 1], R[3 * a + 2], qa);
            qq += qa * qa;
        }
        __syncthreads();
        int cnt = min(RT, s1 - base);
        #pragma unroll 4
        for (int t = 0; t < cnt; t++) {
            float4 v = tile[t];
            float kdp = kvx * v.x + kvy * v.y + kvz * v.z;
            float s, c;
            __sincosf(kdp, &s, &c);
            cr = fmaf(v.w, c, cr);
            ci = fmaf(v.w, s, ci);
        }
        __syncthreads();
    }

    float part = (cr * cr + ci * ci) * w;
    part = block_sum(part, red);
    __syncthreads();
    float qqs = 0.f;
    if (blockIdx.y == 0) qqs = block_sum(qq, red);

    if (tid == 0) {
        float v = KE * g_pref[m] * part;
        if (blockIdx.y == 0)
            v -= KE * sqrtf(ALPHA / 3.14159265358979f) * qqs;
        atomicAdd(&out[m], v);
    }
}

// =====================================================================
extern "C" void kernel_launch(void* const* d_in, const int* in_sizes, int n_in,
                              void* d_out, int out_size)
{
    const float* q     = (const float*)d_in[0];      // partial_charges [A,1]
    const float* Rij   = (const float*)d_in[1];      // [P,3]
    const float* R     = (const float*)d_in[2];      // [A,3]
    const float* cell  = (const float*)d_in[3];      // [M,3,3]
    const float* kvecs = (const float*)d_in[4];      // [K,3]
    const int*   idx_m = (const int*)d_in[5];        // [A] int32
    const int*   idx_i = (const int*)d_in[6];        // [P] int32
    const int*   idx_j = (const int*)d_in[7];        // [P] int32
    float* out = (float*)d_out;

    int natoms = in_sizes[0];
    int npairs = in_sizes[1] / 3;
    int nk     = in_sizes[4] / 3;
    int nmol   = in_sizes[3] / 9;

    if (natoms > MAXA) natoms = MAXA;   // problem-fixed sizes; safety clamp

    int sblocks = (natoms + 255) / 256;
    if (sblocks < 1) sblocks = 1;
    setup_kernel<<<sblocks, 256>>>(q, cell, kvecs, idx_m, natoms, nk, out);

    int nhalf_max = (nk + 1) / 2;
    int gy = (nhalf_max + RT - 1) / RT;
    dim3 grid(nmol, gy);

    // One-time host resources for the capture-legal fork/join pattern.
    static cudaStream_t s2 = nullptr;
    static cudaEvent_t  e1 = nullptr, e2 = nullptr;
    static bool init_ok = false;
    static bool init_tried = false;
    if (!init_tried) {
        init_tried = true;
        init_ok = (cudaStreamCreateWithFlags(&s2, cudaStreamNonBlocking) == cudaSuccess) &&
                  (cudaEventCreateWithFlags(&e1, cudaEventDisableTiming) == cudaSuccess) &&
                  (cudaEventCreateWithFlags(&e2, cudaEventDisableTiming) == cudaSuccess);
    }

    if (init_ok) {
        // fork: recip on s2 concurrently with real(+fold) on the capture stream
        cudaEventRecord(e1, 0);
        cudaStreamWaitEvent(s2, e1, 0);
        recip_kernel<<<grid, RT, 0, s2>>>(R, q, kvecs, out);
        real_kernel<<<RB, RTH>>>(Rij, idx_i, idx_j, q, npairs);
        fold_kernel<<<1, NMOL>>>(out);
        cudaEventRecord(e2, s2);
        cudaStreamWaitEvent(0, e2, 0);   // join
    } else {
        real_kernel<<<RB, RTH>>>(Rij, idx_i, idx_j, q, npairs);
        fold_kernel<<<1, NMOL>>>(out);
        recip_kernel<<<grid, RT>>>(R, q, kvecs, out);
    }
}

// round 9
// speedup vs baseline: 1.6805x; 1.6805x over previous
#include <cuda_runtime.h>
#include <cuda_bf16.h>
#include <math.h>

#define KE       14.3996f
#define ALPHA    0.3f
#define CUTOFF   10.0f
#define NMOL     64
#define MAXA     100000
#define MAXK     1024
#define TWOPI    6.283185307179586f
#define SQA      0.5477225575051661f   /* sqrt(0.3) */

#define RB   1184         /* real-space blocks (148 SMs x 8) */
#define RTH  256          /* real-space threads per block    */
#define BZ   4            /* recip atom-split factor         */

// -------- device scratch (no allocation allowed) --------
__device__ float  g_recip[NMOL][9];     // B[d][e] row-major: kv_e = sum_d g_d * B[d*3+e]
__device__ float  g_pref[NMOL];         // 2*pi / |det(cell)|
__device__ int    g_start[NMOL + 1];    // atom range per molecule (idx_m sorted)
__device__ int    g_halfk[MAXK];        // indices of half-space k vectors (any order)
__device__ int    g_nhalf;
__device__ float  g_yatom[MAXA];        // per-atom real-space partials

// =====================================================================
// Zero per-atom accumulator (only dependency of real_kernel).
// =====================================================================
__global__ __launch_bounds__(256) void zero_kernel(int natoms)
{
    int a = blockIdx.x * 256 + threadIdx.x;
    if (a < natoms) g_yatom[a] = 0.0f;
}

// =====================================================================
// Setup: zero out, per-molecule recip boxes, molecule offsets
// (parallel boundary detection), half-k list (parallel compaction).
// Indices are int32.
// =====================================================================
__global__ __launch_bounds__(256) void setup_kernel(
    const float* __restrict__ cell, const float* __restrict__ kvecs,
    const int* __restrict__ idx_m, int natoms, int nk, float* __restrict__ out)
{
    int tid = threadIdx.x;
    if (blockIdx.x == 0) {
        __shared__ int cnt;
        if (tid == 0) cnt = 0;
        if (tid < NMOL) {
            // 3x3 inverse for cell m = tid
            const float* a = cell + 9 * tid;
            float a00 = a[0], a01 = a[1], a02 = a[2];
            float a10 = a[3], a11 = a[4], a12 = a[5];
            float a20 = a[6], a21 = a[7], a22 = a[8];
            float c00 = a11 * a22 - a12 * a21;
            float c01 = a02 * a21 - a01 * a22;
            float c02 = a01 * a12 - a02 * a11;
            float c10 = a12 * a20 - a10 * a22;
            float c11 = a00 * a22 - a02 * a20;
            float c12 = a02 * a10 - a00 * a12;
            float c20 = a10 * a21 - a11 * a20;
            float c21 = a01 * a20 - a00 * a21;
            float c22 = a00 * a11 - a01 * a10;
            float det = a00 * c00 + a01 * c10 + a02 * c20;
            float id = 1.0f / det;
            float i00 = c00 * id, i01 = c01 * id, i02 = c02 * id;
            float i10 = c10 * id, i11 = c11 * id, i12 = c12 * id;
            float i20 = c20 * id, i21 = c21 * id, i22 = c22 * id;
            // B[d*3+e] = 2*pi * inv[e][d]  (recip_box = 2*pi * inv(cell)^T)
            g_recip[tid][0] = TWOPI * i00;
            g_recip[tid][1] = TWOPI * i10;
            g_recip[tid][2] = TWOPI * i20;
            g_recip[tid][3] = TWOPI * i01;
            g_recip[tid][4] = TWOPI * i11;
            g_recip[tid][5] = TWOPI * i21;
            g_recip[tid][6] = TWOPI * i02;
            g_recip[tid][7] = TWOPI * i12;
            g_recip[tid][8] = TWOPI * i22;
            g_pref[tid] = TWOPI / fabsf(det);
            out[tid] = 0.0f;
        }
        __syncthreads();
        // parallel half-space k compaction (sign-symmetric set: one of {k,-k})
        for (int k = tid; k < nk; k += 256) {
            float gx = kvecs[3 * k], gy = kvecs[3 * k + 1], gz = kvecs[3 * k + 2];
            bool sel = (gz > 0.0f) ||
                       (gz == 0.0f && gy > 0.0f) ||
                       (gz == 0.0f && gy == 0.0f && gx > 0.0f);
            if (sel) {
                int p = atomicAdd(&cnt, 1);
                if (p < MAXK) g_halfk[p] = k;
            }
        }
        __syncthreads();
        if (tid == 0) g_nhalf = min(cnt, MAXK);
    }
    // parallel g_start boundary detection (idx_m sorted ascending)
    for (int a = blockIdx.x * blockDim.x + tid; a < natoms; a += gridDim.x * blockDim.x) {
        int m = idx_m[a];
        int mn = (a + 1 < natoms) ? idx_m[a + 1] : NMOL;
        for (int mm = m + 1; mm <= mn; mm++) g_start[mm] = a + 1;
        if (a == 0)
            for (int mm = 0; mm <= m; mm++) g_start[mm] = 0;
    }
}

// =====================================================================
// Real space v3: no smem, full occupancy. Per pair: two 4B gathers +
// one global REDG (atomicAdd, no return) into the per-atom accumulator.
// =====================================================================
__device__ __forceinline__ void do_pair(
    float x, float y, float z, int i, int j,
    const float* __restrict__ q, float frcut, float cut2)
{
    float d2 = fmaf(x, x, fmaf(y, y, z * z));
    if (d2 <= cut2) {
        float qi = __ldg(&q[i]);
        float qj = __ldg(&q[j]);
        float d = sqrtf(d2);
        float fr = __fdividef(erfcf(SQA * d), d) - frcut;
        atomicAdd(&g_yatom[i], qi * qj * fr);       // REDG, spread addresses
    }
}

__global__ __launch_bounds__(RTH) void real_kernel(
    const float* __restrict__ Rij,
    const int* __restrict__ idx_i, const int* __restrict__ idx_j,
    const float* __restrict__ q, int npairs)
{
    int tid = threadIdx.x;
    const float frcut = erfcf(SQA * CUTOFF) / CUTOFF;
    const float cut2 = CUTOFF * CUTOFF;

    int nquad = npairs >> 2;
    const float4* r4 = (const float4*)Rij;
    const int4*   i4 = (const int4*)idx_i;
    const int4*   j4 = (const int4*)idx_j;

    for (int qd = blockIdx.x * RTH + tid; qd < nquad; qd += RB * RTH) {
        float4 A = r4[3 * qd], B = r4[3 * qd + 1], C = r4[3 * qd + 2];
        int4 ii = i4[qd];
        int4 jj = j4[qd];
        do_pair(A.x, A.y, A.z, ii.x, jj.x, q, frcut, cut2);
        do_pair(A.w, B.x, B.y, ii.y, jj.y, q, frcut, cut2);
        do_pair(B.z, B.w, C.x, ii.z, jj.z, q, frcut, cut2);
        do_pair(C.y, C.z, C.w, ii.w, jj.w, q, frcut, cut2);
    }
    // remainder pairs (npairs not divisible by 4)
    int rem = npairs - (nquad << 2);
    if (blockIdx.x == 0 && tid < rem) {
        int p = (nquad << 2) + tid;
        do_pair(Rij[3 * p], Rij[3 * p + 1], Rij[3 * p + 2],
                idx_i[p], idx_j[p], q, frcut, cut2);
    }
}

// =====================================================================
// Fold: segment-sum g_yatom over each molecule's (sorted) atom range.
// =====================================================================
__global__ __launch_bounds__(256) void fold_kernel(float* __restrict__ out)
{
    __shared__ float red[8];
    int m = blockIdx.x;
    int tid = threadIdx.x;
    int s0 = g_start[m], s1 = g_start[m + 1];
    float s = 0.0f;
    for (int a = s0 + tid; a < s1; a += 256) s += g_yatom[a];
    #pragma unroll
    for (int o = 16; o; o >>= 1) s += __shfl_down_sync(0xffffffffu, s, o);
    int wid = tid >> 5, lid = tid & 31;
    if (lid == 0) red[wid] = s;
    __syncthreads();
    if (wid == 0) {
        s = (lid < 8) ? red[lid] : 0.0f;
        #pragma unroll
        for (int o = 4; o; o >>= 1) s += __shfl_down_sync(0xffffffffu, s, o);
        if (lid == 0) atomicAdd(&out[m], 0.5f * KE * s);
    }
}

// =====================================================================
// Reciprocal space: block = (molecule, k-chunk, atom-slice). Thread = one
// half-space k; loops over its atom slice via shared float4 tiles.
// +-k symmetry => x2 weight. Self-energy folded into y==0 blocks.
// =====================================================================
#define RT 256

__device__ __forceinline__ float block_sum(float v, float* sh)
{
    #pragma unroll
    for (int o = 16; o; o >>= 1) v += __shfl_down_sync(0xffffffffu, v, o);
    int wid = threadIdx.x >> 5, lid = threadIdx.x & 31;
    if (lid == 0) sh[wid] = v;
    __syncthreads();
    if (wid == 0) {
        v = (lid < (RT >> 5)) ? sh[lid] : 0.0f;
        #pragma unroll
        for (int o = 4; o; o >>= 1) v += __shfl_down_sync(0xffffffffu, v, o);
    }
    return v;   // valid on thread 0
}

__global__ __launch_bounds__(RT) void recip_kernel(
    const float* __restrict__ R, const float* __restrict__ q,
    const float* __restrict__ kvecs, float* __restrict__ out)
{
    int m = blockIdx.x;
    int tid = threadIdx.x;
    int hk = blockIdx.y * RT + tid;
    int z  = blockIdx.z;

    float kvx = 0.f, kvy = 0.f, kvz = 0.f, w = 0.f;
    if (hk < g_nhalf) {
        int k = g_halfk[hk];
        float gx = kvecs[3 * k], gy = kvecs[3 * k + 1], gz = kvecs[3 * k + 2];
        const float* B = g_recip[m];
        kvx = gx * B[0] + gy * B[3] + gz * B[6];
        kvy = gx * B[1] + gy * B[4] + gz * B[7];
        kvz = gx * B[2] + gy * B[5] + gz * B[8];
        float ksq = kvx * kvx + kvy * kvy + kvz * kvz;
        w = 2.0f * expf(-0.25f * ksq / ALPHA) / ksq;   // x2: +-k symmetry
    }

    // atom slice z of BZ for this molecule
    int m0 = g_start[m], m1 = g_start[m + 1];
    int len = m1 - m0;
    int per = (len + BZ - 1) / BZ;
    int s0 = m0 + z * per;
    int s1 = min(m1, s0 + per);

    __shared__ float4 tile[RT];
    __shared__ float red[RT >> 5];

    float cr = 0.f, ci = 0.f, qq = 0.f;
    for (int base = s0; base < s1; base += RT) {
        int a = base + tid;
        if (a < s1) {
            float qa = q[a];
            tile[tid] = make_float4(R[3 * a], R[3 * a + 1], R[3 * a + 2], qa);
            qq += qa * qa;
        }
        __syncthreads();
        int cnt = min(RT, s1 - base);
        #pragma unroll 4
        for (int t = 0; t < cnt; t++) {
            float4 v = tile[t];
            float kdp = kvx * v.x + kvy * v.y + kvz * v.z;
            float s, c;
            __sincosf(kdp, &s, &c);
            cr = fmaf(v.w, c, cr);
            ci = fmaf(v.w, s, ci);
        }
        __syncthreads();
    }

    // NOTE: |S_m(k)|^2 does NOT split over atom slices, so publish the slice
    // contribution as a complex pair and square in a tiny epilogue.  To keep
    // one-kernel simplicity we instead restrict BZ slicing to the structure
    // factor via global complex partials:
    //   g_sf[m][hk] accumulation would need nk*nmol*8B = 512KB scratch and a
    //   second pass.  Simpler: each block computes its slice's (cr,ci) and
    //   atomically accumulates into g_sf, then y-extent epilogue.  To avoid
    //   the extra pass entirely we use BZ==1 semantics when slicing is
    //   disabled at launch.  (grid.z == 1 => this path is exact.)
    if (gridDim.z == 1) {
        float part = (cr * cr + ci * ci) * w;
        part = block_sum(part, red);
        __syncthreads();
        float qqs = 0.f;
        if (blockIdx.y == 0) qqs = block_sum(qq, red);
        if (tid == 0) {
            float v = KE * g_pref[m] * part;
            if (blockIdx.y == 0)
                v -= KE * sqrtf(ALPHA / 3.14159265358979f) * qqs;
            atomicAdd(&out[m], v);
        }
    }
}

// ---- sliced structure-factor path: partial (cr,ci) per (m,hk,z) ----
__device__ float2 g_sf[NMOL][MAXK];     // complex structure factor partials
__device__ float  g_qq[NMOL];           // per-molecule sum q^2 partials

__global__ __launch_bounds__(256) void sfzero_kernel(void)
{
    int i = blockIdx.x * 256 + threadIdx.x;
    if (i < NMOL * MAXK) ((float2*)g_sf)[i] = make_float2(0.f, 0.f);
    if (i < NMOL) g_qq[i] = 0.0f;
}

__global__ __launch_bounds__(RT) void recip_sf_kernel(
    const float* __restrict__ R, const float* __restrict__ q,
    const float* __restrict__ kvecs)
{
    int m = blockIdx.x;
    int tid = threadIdx.x;
    int hk = blockIdx.y * RT + tid;
    int z  = blockIdx.z;

    float kvx = 0.f, kvy = 0.f, kvz = 0.f;
    if (hk < g_nhalf) {
        int k = g_halfk[hk];
        float gx = kvecs[3 * k], gy = kvecs[3 * k + 1], gz = kvecs[3 * k + 2];
        const float* B = g_recip[m];
        kvx = gx * B[0] + gy * B[3] + gz * B[6];
        kvy = gx * B[1] + gy * B[4] + gz * B[7];
        kvz = gx * B[2] + gy * B[5] + gz * B[8];
    }

    int m0 = g_start[m], m1 = g_start[m + 1];
    int len = m1 - m0;
    int per = (len + BZ - 1) / BZ;
    int s0 = m0 + z * per;
    int s1 = min(m1, s0 + per);

    __shared__ float4 tile[RT];
    __shared__ float red[RT >> 5];

    float cr = 0.f, ci = 0.f, qq = 0.f;
    for (int base = s0; base < s1; base += RT) {
        int a = base + tid;
        if (a < s1) {
            float qa = q[a];
            tile[tid] = make_float4(R[3 * a], R[3 * a + 1], R[3 * a + 2], qa);
            qq += qa * qa;
        }
        __syncthreads();
        int cnt = min(RT, s1 - base);
        #pragma unroll 4
        for (int t = 0; t < cnt; t++) {
            float4 v = tile[t];
            float kdp = kvx * v.x + kvy * v.y + kvz * v.z;
            float s, c;
            __sincosf(kdp, &s, &c);
            cr = fmaf(v.w, c, cr);
            ci = fmaf(v.w, s, ci);
        }
        __syncthreads();
    }

    if (hk < g_nhalf) {
        atomicAdd(&g_sf[m][hk].x, cr);
        atomicAdd(&g_sf[m][hk].y, ci);
    }
    if (blockIdx.y == 0) {
        float qqs = block_sum(qq, red);
        if (tid == 0) atomicAdd(&g_qq[m], qqs);
    }
}

__global__ __launch_bounds__(RT) void recip_epi_kernel(
    const float* __restrict__ kvecs, float* __restrict__ out)
{
    __shared__ float red[RT >> 5];
    int m = blockIdx.x;
    int tid = threadIdx.x;

    float acc = 0.f;
    for (int hk = tid; hk < g_nhalf; hk += RT) {
        int k = g_halfk[hk];
        float gx = kvecs[3 * k], gy = kvecs[3 * k + 1], gz = kvecs[3 * k + 2];
        const float* B = g_recip[m];
        float kvx = gx * B[0] + gy * B[3] + gz * B[6];
        float kvy = gx * B[1] + gy * B[4] + gz * B[7];
        float kvz = gx * B[2] + gy * B[5] + gz * B[8];
        float ksq = kvx * kvx + kvy * kvy + kvz * kvz;
        float w = 2.0f * expf(-0.25f * ksq / ALPHA) / ksq;
        float2 sf = g_sf[m][hk];
        acc = fmaf((sf.x * sf.x + sf.y * sf.y), w, acc);
    }
    acc = block_sum(acc, red);
    if (tid == 0) {
        float v = KE * (g_pref[m] * acc
                        - sqrtf(ALPHA / 3.14159265358979f) * g_qq[m]);
        atomicAdd(&out[m], v);
    }
}

// =====================================================================
extern "C" void kernel_launch(void* const* d_in, const int* in_sizes, int n_in,
                              void* d_out, int out_size)
{
    const float* q     = (const float*)d_in[0];      // partial_charges [A,1]
    const float* Rij   = (const float*)d_in[1];      // [P,3]
    const float* R     = (const float*)d_in[2];      // [A,3]
    const float* cell  = (const float*)d_in[3];      // [M,3,3]
    const float* kvecs = (const float*)d_in[4];      // [K,3]
    const int*   idx_m = (const int*)d_in[5];        // [A] int32
    const int*   idx_i = (const int*)d_in[6];        // [P] int32
    const int*   idx_j = (const int*)d_in[7];        // [P] int32
    float* out = (float*)d_out;

    int natoms = in_sizes[0];
    int npairs = in_sizes[1] / 3;
    int nk     = in_sizes[4] / 3;
    int nmol   = in_sizes[3] / 9;

    if (natoms > MAXA) natoms = MAXA;   // problem-fixed sizes; safety clamp

    int sblocks = (natoms + 255) / 256;
    if (sblocks < 1) sblocks = 1;

    int nhalf_max = (nk + 1) / 2;
    int gy = (nhalf_max + RT - 1) / RT;

    // One-time host resources for the capture-legal fork/join pattern.
    static cudaStream_t s2 = nullptr;
    static cudaEvent_t  e1 = nullptr, e2 = nullptr, eS = nullptr;
    static bool init_ok = false;
    static bool init_tried = false;
    if (!init_tried) {
        init_tried = true;
        init_ok = (cudaStreamCreateWithFlags(&s2, cudaStreamNonBlocking) == cudaSuccess) &&
                  (cudaEventCreateWithFlags(&e1, cudaEventDisableTiming) == cudaSuccess) &&
                  (cudaEventCreateWithFlags(&e2, cudaEventDisableTiming) == cudaSuccess) &&
                  (cudaEventCreateWithFlags(&eS, cudaEventDisableTiming) == cudaSuccess);
    }

    int sfblocks = (NMOL * MAXK + 255) / 256;

    if (init_ok) {
        // fork
        cudaEventRecord(e1, 0);
        cudaStreamWaitEvent(s2, e1, 0);
        // s2: setup -> sliced structure factor -> epilogue
        setup_kernel<<<sblocks, 256, 0, s2>>>(cell, kvecs, idx_m, natoms, nk, out);
        sfzero_kernel<<<sfblocks, 256, 0, s2>>>();
        cudaEventRecord(eS, s2);
        {
            dim3 grid(nmol, gy, BZ);
            recip_sf_kernel<<<grid, RT, 0, s2>>>(R, q, kvecs);
            recip_epi_kernel<<<nmol, RT, 0, s2>>>(kvecs, out);
        }
        // stream 0: zero -> real -> (after setup) fold
        zero_kernel<<<sblocks, 256>>>(natoms);
        real_kernel<<<RB, RTH>>>(Rij, idx_i, idx_j, q, npairs);
        cudaStreamWaitEvent(0, eS, 0);
        fold_kernel<<<NMOL, 256>>>(out);
        // join
        cudaEventRecord(e2, s2);
        cudaStreamWaitEvent(0, e2, 0);
    } else {
        setup_kernel<<<sblocks, 256>>>(cell, kvecs, idx_m, natoms, nk, out);
        zero_kernel<<<sblocks, 256>>>(natoms);
        real_kernel<<<RB, RTH>>>(Rij, idx_i, idx_j, q, npairs);
        fold_kernel<<<NMOL, 256>>>(out);
        dim3 grid(nmol, gy, 1);
        recip_kernel<<<grid, RT>>>(R, q, kvecs, out);
    }
}

// round 14
// speedup vs baseline: 1.9049x; 1.1335x over previous
#include <cuda_runtime.h>
#include <cuda_bf16.h>
#include <math.h>

#define KE       14.3996f
#define ALPHA    0.3f
#define CUTOFF   10.0f
#define NMOL     64
#define MAXA     100000
#define MAXK     1024
#define TWOPI    6.283185307179586f
#define SQA      0.5477225575051661f   /* sqrt(0.3) */

#define RB   1184         /* real-space blocks (148 SMs x 8) */
#define RTH  256          /* real-space threads per block    */
#define BZ   4            /* recip atom-split factor         */

// -------- device scratch (no allocation allowed) --------
__device__ float  g_recip[NMOL][9];     // B[d][e] row-major: kv_e = sum_d g_d * B[d*3+e]
__device__ float  g_pref[NMOL];         // 2*pi / |det(cell)|
__device__ int    g_start[NMOL + 1];    // atom range per molecule (idx_m sorted)
__device__ int    g_halfk[MAXK];        // indices of half-space k vectors (any order)
__device__ int    g_nhalf;
__device__ float  g_yatom[MAXA];        // per-atom real-space partials (q_i factored OUT)

// =====================================================================
// Zero per-atom accumulator (only dependency of real_kernel).
// =====================================================================
__global__ __launch_bounds__(256) void zero_kernel(int natoms)
{
    int a = blockIdx.x * 256 + threadIdx.x;
    if (a < natoms) g_yatom[a] = 0.0f;
}

// =====================================================================
// Setup: zero out, per-molecule recip boxes, molecule offsets
// (parallel boundary detection), half-k list (parallel compaction).
// Indices are int32.
// =====================================================================
__global__ __launch_bounds__(256) void setup_kernel(
    const float* __restrict__ cell, const float* __restrict__ kvecs,
    const int* __restrict__ idx_m, int natoms, int nk, float* __restrict__ out)
{
    int tid = threadIdx.x;
    if (blockIdx.x == 0) {
        __shared__ int cnt;
        if (tid == 0) cnt = 0;
        if (tid < NMOL) {
            // 3x3 inverse for cell m = tid
            const float* a = cell + 9 * tid;
            float a00 = a[0], a01 = a[1], a02 = a[2];
            float a10 = a[3], a11 = a[4], a12 = a[5];
            float a20 = a[6], a21 = a[7], a22 = a[8];
            float c00 = a11 * a22 - a12 * a21;
            float c01 = a02 * a21 - a01 * a22;
            float c02 = a01 * a12 - a02 * a11;
            float c10 = a12 * a20 - a10 * a22;
            float c11 = a00 * a22 - a02 * a20;
            float c12 = a02 * a10 - a00 * a12;
            float c20 = a10 * a21 - a11 * a20;
            float c21 = a01 * a20 - a00 * a21;
            float c22 = a00 * a11 - a01 * a10;
            float det = a00 * c00 + a01 * c10 + a02 * c20;
            float id = 1.0f / det;
            float i00 = c00 * id, i01 = c01 * id, i02 = c02 * id;
            float i10 = c10 * id, i11 = c11 * id, i12 = c12 * id;
            float i20 = c20 * id, i21 = c21 * id, i22 = c22 * id;
            // B[d*3+e] = 2*pi * inv[e][d]  (recip_box = 2*pi * inv(cell)^T)
            g_recip[tid][0] = TWOPI * i00;
            g_recip[tid][1] = TWOPI * i10;
            g_recip[tid][2] = TWOPI * i20;
            g_recip[tid][3] = TWOPI * i01;
            g_recip[tid][4] = TWOPI * i11;
            g_recip[tid][5] = TWOPI * i21;
            g_recip[tid][6] = TWOPI * i02;
            g_recip[tid][7] = TWOPI * i12;
            g_recip[tid][8] = TWOPI * i22;
            g_pref[tid] = TWOPI / fabsf(det);
            out[tid] = 0.0f;
        }
        __syncthreads();
        // parallel half-space k compaction (sign-symmetric set: one of {k,-k})
        for (int k = tid; k < nk; k += 256) {
            float gx = kvecs[3 * k], gy = kvecs[3 * k + 1], gz = kvecs[3 * k + 2];
            bool sel = (gz > 0.0f) ||
                       (gz == 0.0f && gy > 0.0f) ||
                       (gz == 0.0f && gy == 0.0f && gx > 0.0f);
            if (sel) {
                int p = atomicAdd(&cnt, 1);
                if (p < MAXK) g_halfk[p] = k;
            }
        }
        __syncthreads();
        if (tid == 0) g_nhalf = min(cnt, MAXK);
    }
    // parallel g_start boundary detection (idx_m sorted ascending)
    for (int a = blockIdx.x * blockDim.x + tid; a < natoms; a += gridDim.x * blockDim.x) {
        int m = idx_m[a];
        int mn = (a + 1 < natoms) ? idx_m[a + 1] : NMOL;
        for (int mm = m + 1; mm <= mn; mm++) g_start[mm] = a + 1;
        if (a == 0)
            for (int mm = 0; mm <= m; mm++) g_start[mm] = 0;
    }
}

// =====================================================================
// Real space v4: q_i factored out of the per-atom segment sum =>
// per pair only ONE random gather (q[j]) + ONE RED (g_yatom[i]).
// No smem, full occupancy.
// =====================================================================
__device__ __forceinline__ void do_pair(
    float x, float y, float z, int i, int j,
    const float* __restrict__ q, float frcut, float cut2)
{
    float d2 = fmaf(x, x, fmaf(y, y, z * z));
    if (d2 <= cut2) {
        float qj = __ldg(&q[j]);
        float d = sqrtf(d2);
        float fr = __fdividef(erfcf(SQA * d), d) - frcut;
        atomicAdd(&g_yatom[i], qj * fr);            // REDG, q_i applied in fold
    }
}

__global__ __launch_bounds__(RTH) void real_kernel(
    const float* __restrict__ Rij,
    const int* __restrict__ idx_i, const int* __restrict__ idx_j,
    const float* __restrict__ q, int npairs)
{
    int tid = threadIdx.x;
    const float frcut = erfcf(SQA * CUTOFF) / CUTOFF;
    const float cut2 = CUTOFF * CUTOFF;

    int nquad = npairs >> 2;
    const float4* r4 = (const float4*)Rij;
    const int4*   i4 = (const int4*)idx_i;
    const int4*   j4 = (const int4*)idx_j;

    for (int qd = blockIdx.x * RTH + tid; qd < nquad; qd += RB * RTH) {
        float4 A = r4[3 * qd], B = r4[3 * qd + 1], C = r4[3 * qd + 2];
        int4 ii = i4[qd];
        int4 jj = j4[qd];
        do_pair(A.x, A.y, A.z, ii.x, jj.x, q, frcut, cut2);
        do_pair(A.w, B.x, B.y, ii.y, jj.y, q, frcut, cut2);
        do_pair(B.z, B.w, C.x, ii.z, jj.z, q, frcut, cut2);
        do_pair(C.y, C.z, C.w, ii.w, jj.w, q, frcut, cut2);
    }
    // remainder pairs (npairs not divisible by 4)
    int rem = npairs - (nquad << 2);
    if (blockIdx.x == 0 && tid < rem) {
        int p = (nquad << 2) + tid;
        do_pair(Rij[3 * p], Rij[3 * p + 1], Rij[3 * p + 2],
                idx_i[p], idx_j[p], q, frcut, cut2);
    }
}

// =====================================================================
// Fold: y_mol = 0.5*KE * sum_a q[a] * g_yatom[a] over molecule range.
// Coalesced; the q_i multiply lives here (factored out of real_kernel).
// =====================================================================
__global__ __launch_bounds__(256) void fold_kernel(
    const float* __restrict__ q, float* __restrict__ out)
{
    __shared__ float red[8];
    int m = blockIdx.x;
    int tid = threadIdx.x;
    int s0 = g_start[m], s1 = g_start[m + 1];
    float s = 0.0f;
    for (int a = s0 + tid; a < s1; a += 256) s += q[a] * g_yatom[a];
    #pragma unroll
    for (int o = 16; o; o >>= 1) s += __shfl_down_sync(0xffffffffu, s, o);
    int wid = tid >> 5, lid = tid & 31;
    if (lid == 0) red[wid] = s;
    __syncthreads();
    if (wid == 0) {
        s = (lid < 8) ? red[lid] : 0.0f;
        #pragma unroll
        for (int o = 4; o; o >>= 1) s += __shfl_down_sync(0xffffffffu, s, o);
        if (lid == 0) atomicAdd(&out[m], 0.5f * KE * s);
    }
}

// =====================================================================
// Reciprocal space (sliced structure factor): block = (mol, k-chunk,
// atom-slice); thread = one half-space k; +-k symmetry => x2 weight.
// =====================================================================
#define RT 256

__device__ __forceinline__ float block_sum(float v, float* sh)
{
    #pragma unroll
    for (int o = 16; o; o >>= 1) v += __shfl_down_sync(0xffffffffu, v, o);
    int wid = threadIdx.x >> 5, lid = threadIdx.x & 31;
    if (lid == 0) sh[wid] = v;
    __syncthreads();
    if (wid == 0) {
        v = (lid < (RT >> 5)) ? sh[lid] : 0.0f;
        #pragma unroll
        for (int o = 4; o; o >>= 1) v += __shfl_down_sync(0xffffffffu, v, o);
    }
    return v;   // valid on thread 0
}

__device__ float2 g_sf[NMOL][MAXK];     // complex structure factor partials
__device__ float  g_qq[NMOL];           // per-molecule sum q^2 partials

__global__ __launch_bounds__(256) void sfzero_kernel(void)
{
    int i = blockIdx.x * 256 + threadIdx.x;
    if (i < NMOL * MAXK) ((float2*)g_sf)[i] = make_float2(0.f, 0.f);
    if (i < NMOL) g_qq[i] = 0.0f;
}

__global__ __launch_bounds__(RT) void recip_sf_kernel(
    const float* __restrict__ R, const float* __restrict__ q,
    const float* __restrict__ kvecs)
{
    int m = blockIdx.x;
    int tid = threadIdx.x;
    int hk = blockIdx.y * RT + tid;
    int z  = blockIdx.z;

    float kvx = 0.f, kvy = 0.f, kvz = 0.f;
    if (hk < g_nhalf) {
        int k = g_halfk[hk];
        float gx = kvecs[3 * k], gy = kvecs[3 * k + 1], gz = kvecs[3 * k + 2];
        const float* B = g_recip[m];
        kvx = gx * B[0] + gy * B[3] + gz * B[6];
        kvy = gx * B[1] + gy * B[4] + gz * B[7];
        kvz = gx * B[2] + gy * B[5] + gz * B[8];
    }

    int m0 = g_start[m], m1 = g_start[m + 1];
    int len = m1 - m0;
    int per = (len + BZ - 1) / BZ;
    int s0 = m0 + z * per;
    int s1 = min(m1, s0 + per);

    __shared__ float4 tile[RT];
    __shared__ float red[RT >> 5];

    float cr = 0.f, ci = 0.f, qq = 0.f;
    for (int base = s0; base < s1; base += RT) {
        int a = base + tid;
        if (a < s1) {
            float qa = q[a];
            tile[tid] = make_float4(R[3 * a], R[3 * a + 1], R[3 * a + 2], qa);
            qq += qa * qa;
        }
        __syncthreads();
        int cnt = min(RT, s1 - base);
        #pragma unroll 4
        for (int t = 0; t < cnt; t++) {
            float4 v = tile[t];
            float kdp = kvx * v.x + kvy * v.y + kvz * v.z;
            float s, c;
            __sincosf(kdp, &s, &c);
            cr = fmaf(v.w, c, cr);
            ci = fmaf(v.w, s, ci);
        }
        __syncthreads();
    }

    if (hk < g_nhalf) {
        atomicAdd(&g_sf[m][hk].x, cr);
        atomicAdd(&g_sf[m][hk].y, ci);
    }
    if (blockIdx.y == 0) {
        float qqs = block_sum(qq, red);
        if (tid == 0) atomicAdd(&g_qq[m], qqs);
    }
}

__global__ __launch_bounds__(RT) void recip_epi_kernel(
    const float* __restrict__ kvecs, float* __restrict__ out)
{
    __shared__ float red[RT >> 5];
    int m = blockIdx.x;
    int tid = threadIdx.x;

    float acc = 0.f;
    for (int hk = tid; hk < g_nhalf; hk += RT) {
        int k = g_halfk[hk];
        float gx = kvecs[3 * k], gy = kvecs[3 * k + 1], gz = kvecs[3 * k + 2];
        const float* B = g_recip[m];
        float kvx = gx * B[0] + gy * B[3] + gz * B[6];
        float kvy = gx * B[1] + gy * B[4] + gz * B[7];
        float kvz = gx * B[2] + gy * B[5] + gz * B[8];
        float ksq = kvx * kvx + kvy * kvy + kvz * kvz;
        float w = 2.0f * expf(-0.25f * ksq / ALPHA) / ksq;   // x2: +-k symmetry
        float2 sf = g_sf[m][hk];
        acc = fmaf((sf.x * sf.x + sf.y * sf.y), w, acc);
    }
    acc = block_sum(acc, red);
    if (tid == 0) {
        float v = KE * (g_pref[m] * acc
                        - sqrtf(ALPHA / 3.14159265358979f) * g_qq[m]);
        atomicAdd(&out[m], v);
    }
}

// =====================================================================
extern "C" void kernel_launch(void* const* d_in, const int* in_sizes, int n_in,
                              void* d_out, int out_size)
{
    const float* q     = (const float*)d_in[0];      // partial_charges [A,1]
    const float* Rij   = (const float*)d_in[1];      // [P,3]
    const float* R     = (const float*)d_in[2];      // [A,3]
    const float* cell  = (const float*)d_in[3];      // [M,3,3]
    const float* kvecs = (const float*)d_in[4];      // [K,3]
    const int*   idx_m = (const int*)d_in[5];        // [A] int32
    const int*   idx_i = (const int*)d_in[6];        // [P] int32
    const int*   idx_j = (const int*)d_in[7];        // [P] int32
    float* out = (float*)d_out;

    int natoms = in_sizes[0];
    int npairs = in_sizes[1] / 3;
    int nk     = in_sizes[4] / 3;
    int nmol   = in_sizes[3] / 9;

    if (natoms > MAXA) natoms = MAXA;   // problem-fixed sizes; safety clamp

    int sblocks = (natoms + 255) / 256;
    if (sblocks < 1) sblocks = 1;

    int nhalf_max = (nk + 1) / 2;
    int gy = (nhalf_max + RT - 1) / RT;

    // One-time host resources for the capture-legal fork/join pattern.
    static cudaStream_t s2 = nullptr;
    static cudaEvent_t  e1 = nullptr, e2 = nullptr, eS = nullptr;
    static bool init_ok = false;
    static bool init_tried = false;
    if (!init_tried) {
        init_tried = true;
        init_ok = (cudaStreamCreateWithFlags(&s2, cudaStreamNonBlocking) == cudaSuccess) &&
                  (cudaEventCreateWithFlags(&e1, cudaEventDisableTiming) == cudaSuccess) &&
                  (cudaEventCreateWithFlags(&e2, cudaEventDisableTiming) == cudaSuccess) &&
                  (cudaEventCreateWithFlags(&eS, cudaEventDisableTiming) == cudaSuccess);
    }

    int sfblocks = (NMOL * MAXK + 255) / 256;

    if (init_ok) {
        // fork
        cudaEventRecord(e1, 0);
        cudaStreamWaitEvent(s2, e1, 0);
        // s2: setup -> sfzero -> sliced structure factor -> epilogue
        setup_kernel<<<sblocks, 256, 0, s2>>>(cell, kvecs, idx_m, natoms, nk, out);
        sfzero_kernel<<<sfblocks, 256, 0, s2>>>();
        cudaEventRecord(eS, s2);
        {
            dim3 grid(nmol, gy, BZ);
            recip_sf_kernel<<<grid, RT, 0, s2>>>(R, q, kvecs);
            recip_epi_kernel<<<nmol, RT, 0, s2>>>(kvecs, out);
        }
        // stream 0: zero -> real -> (after setup publishes g_start) fold
        zero_kernel<<<sblocks, 256>>>(natoms);
        real_kernel<<<RB, RTH>>>(Rij, idx_i, idx_j, q, npairs);
        cudaStreamWaitEvent(0, eS, 0);
        fold_kernel<<<NMOL, 256>>>(q, out);
        // join
        cudaEventRecord(e2, s2);
        cudaStreamWaitEvent(0, e2, 0);
    } else {
        setup_kernel<<<sblocks, 256>>>(cell, kvecs, idx_m, natoms, nk, out);
        zero_kernel<<<sblocks, 256>>>(natoms);
        real_kernel<<<RB, RTH>>>(Rij, idx_i, idx_j, q, npairs);
        fold_kernel<<<NMOL, 256>>>(q, out);
        sfzero_kernel<<<sfblocks, 256>>>();
        dim3 grid(nmol, gy, BZ);
        recip_sf_kernel<<<grid, RT>>>(R, q, kvecs);
        recip_epi_kernel<<<nmol, RT>>>(kvecs, out);
    }
}

// round 16
// speedup vs baseline: 2.6188x; 1.3747x over previous
#include <cuda_runtime.h>
#include <cuda_bf16.h>
#include <math.h>

#define KE       14.3996f
#define ALPHA    0.3f
#define CUTOFF   10.0f
#define NMOL     64
#define MAXA     100000
#define MAXK     1024
#define TWOPI    6.283185307179586f
#define SQA      0.5477225575051661f   /* sqrt(0.3) */

#define RB   148          /* real-space blocks: 1 per SM, 74 per j-half */
#define RTH  512          /* real-space threads per block               */
#define RBF  1184         /* fallback real blocks                       */
#define RTF  256          /* fallback real threads                      */
#define BZ   4            /* recip atom-split factor                    */

// -------- device scratch (no allocation allowed) --------
__device__ float  g_recip[NMOL][9];     // B[d][e] row-major: kv_e = sum_d g_d * B[d*3+e]
__device__ float  g_pref[NMOL];         // 2*pi / |det(cell)|
__device__ int    g_start[NMOL + 1];    // atom range per molecule (idx_m sorted)
__device__ int    g_halfk[MAXK];        // indices of half-space k vectors (any order)
__device__ int    g_nhalf;
__device__ float  g_yatom[MAXA];        // per-atom real-space partials (q_i factored OUT)

// =====================================================================
// Zero per-atom accumulator (only dependency of real_kernel).
// =====================================================================
__global__ __launch_bounds__(256) void zero_kernel(int natoms)
{
    int a = blockIdx.x * 256 + threadIdx.x;
    if (a < natoms) g_yatom[a] = 0.0f;
}

// =====================================================================
// Setup: zero out, per-molecule recip boxes, molecule offsets
// (parallel boundary detection), half-k list (parallel compaction).
// Indices are int32.
// =====================================================================
__global__ __launch_bounds__(256) void setup_kernel(
    const float* __restrict__ cell, const float* __restrict__ kvecs,
    const int* __restrict__ idx_m, int natoms, int nk, float* __restrict__ out)
{
    int tid = threadIdx.x;
    if (blockIdx.x == 0) {
        __shared__ int cnt;
        if (tid == 0) cnt = 0;
        if (tid < NMOL) {
            // 3x3 inverse for cell m = tid
            const float* a = cell + 9 * tid;
            float a00 = a[0], a01 = a[1], a02 = a[2];
            float a10 = a[3], a11 = a[4], a12 = a[5];
            float a20 = a[6], a21 = a[7], a22 = a[8];
            float c00 = a11 * a22 - a12 * a21;
            float c01 = a02 * a21 - a01 * a22;
            float c02 = a01 * a12 - a02 * a11;
            float c10 = a12 * a20 - a10 * a22;
            float c11 = a00 * a22 - a02 * a20;
            float c12 = a02 * a10 - a00 * a12;
            float c20 = a10 * a21 - a11 * a20;
            float c21 = a01 * a20 - a00 * a21;
            float c22 = a00 * a11 - a01 * a10;
            float det = a00 * c00 + a01 * c10 + a02 * c20;
            float id = 1.0f / det;
            float i00 = c00 * id, i01 = c01 * id, i02 = c02 * id;
            float i10 = c10 * id, i11 = c11 * id, i12 = c12 * id;
            float i20 = c20 * id, i21 = c21 * id, i22 = c22 * id;
            // B[d*3+e] = 2*pi * inv[e][d]  (recip_box = 2*pi * inv(cell)^T)
            g_recip[tid][0] = TWOPI * i00;
            g_recip[tid][1] = TWOPI * i10;
            g_recip[tid][2] = TWOPI * i20;
            g_recip[tid][3] = TWOPI * i01;
            g_recip[tid][4] = TWOPI * i11;
            g_recip[tid][5] = TWOPI * i21;
            g_recip[tid][6] = TWOPI * i02;
            g_recip[tid][7] = TWOPI * i12;
            g_recip[tid][8] = TWOPI * i22;
            g_pref[tid] = TWOPI / fabsf(det);
            out[tid] = 0.0f;
        }
        __syncthreads();
        // parallel half-space k compaction (sign-symmetric set: one of {k,-k})
        for (int k = tid; k < nk; k += 256) {
            float gx = kvecs[3 * k], gy = kvecs[3 * k + 1], gz = kvecs[3 * k + 2];
            bool sel = (gz > 0.0f) ||
                       (gz == 0.0f && gy > 0.0f) ||
                       (gz == 0.0f && gy == 0.0f && gx > 0.0f);
            if (sel) {
                int p = atomicAdd(&cnt, 1);
                if (p < MAXK) g_halfk[p] = k;
            }
        }
        __syncthreads();
        if (tid == 0) g_nhalf = min(cnt, MAXK);
    }
    // parallel g_start boundary detection (idx_m sorted ascending)
    for (int a = blockIdx.x * blockDim.x + tid; a < natoms; a += gridDim.x * blockDim.x) {
        int m = idx_m[a];
        int mn = (a + 1 < natoms) ? idx_m[a + 1] : NMOL;
        for (int mm = m + 1; mm <= mn; mm++) g_start[mm] = a + 1;
        if (a == 0)
            for (int mm = 0; mm <= m; mm++) g_start[mm] = 0;
    }
}

// =====================================================================
// Real space v5: chip split into two j-halves; each block caches its
// half of q (200 KB fp32) in dynamic smem. Per pair: 1 LDS gather
// (smem port) + 1 REDG (only L1tex divergent op). Pair streams read 2x.
// =====================================================================
__device__ __forceinline__ void do_pair(
    float x, float y, float z, int i, int j,
    const float* __restrict__ qsh, int lo, int hi,
    float frcut, float cut2)
{
    if (j >= lo && j < hi) {
        float d2 = fmaf(x, x, fmaf(y, y, z * z));
        if (d2 <= cut2) {
            float qj = qsh[j - lo];                 // LDS, random: smem port
            float d = sqrtf(d2);
            float fr = __fdividef(erfcf(SQA * d), d) - frcut;
            atomicAdd(&g_yatom[i], qj * fr);        // REDG: the one L1tex op
        }
    }
}

__global__ __launch_bounds__(RTH, 1) void real_kernel(
    const float* __restrict__ Rij,
    const int* __restrict__ idx_i, const int* __restrict__ idx_j,
    const float* __restrict__ q, int npairs, int natoms)
{
    extern __shared__ float qsh[];
    int tid = threadIdx.x;

    int half = blockIdx.x & 1;
    int hs = (natoms + 1) >> 1;
    int lo = half * hs;
    int hi = min(natoms, lo + hs);
    int n  = hi - lo;

    // coalesced smem fill of this half's q slice (float4 fast path)
    {
        const float* qb = q + lo;
        int n4 = n >> 2;
        bool al = ((((size_t)qb) & 15) == 0);
        if (al) {
            for (int t = tid; t < n4; t += RTH)
                ((float4*)qsh)[t] = ((const float4*)qb)[t];
            for (int t = (n4 << 2) + tid; t < n; t += RTH) qsh[t] = qb[t];
        } else {
            for (int t = tid; t < n; t += RTH) qsh[t] = qb[t];
        }
    }
    __syncthreads();

    const float frcut = erfcf(SQA * CUTOFF) / CUTOFF;
    const float cut2 = CUTOFF * CUTOFF;

    int nquad = npairs >> 2;
    const float4* r4 = (const float4*)Rij;
    const int4*   i4 = (const int4*)idx_i;
    const int4*   j4 = (const int4*)idx_j;

    int gid = blockIdx.x >> 1;                      // block index within this half
    int gstr = gridDim.x >> 1;                      // blocks per half

    for (int qd = gid * RTH + tid; qd < nquad; qd += gstr * RTH) {
        float4 A = r4[3 * qd], B = r4[3 * qd + 1], C = r4[3 * qd + 2];
        int4 jj = j4[qd];
        int4 ii = i4[qd];
        do_pair(A.x, A.y, A.z, ii.x, jj.x, qsh, lo, hi, frcut, cut2);
        do_pair(A.w, B.x, B.y, ii.y, jj.y, qsh, lo, hi, frcut, cut2);
        do_pair(B.z, B.w, C.x, ii.z, jj.z, qsh, lo, hi, frcut, cut2);
        do_pair(C.y, C.z, C.w, ii.w, jj.w, qsh, lo, hi, frcut, cut2);
    }
    // remainder pairs (npairs not divisible by 4): blocks 0 (half 0) and 1 (half 1)
    int rem = npairs - (nquad << 2);
    if (blockIdx.x < 2 && tid < rem) {
        int p = (nquad << 2) + tid;
        do_pair(Rij[3 * p], Rij[3 * p + 1], Rij[3 * p + 2],
                idx_i[p], idx_j[p], qsh, lo, hi, frcut, cut2);
    }
}

// ---- fallback (measured 121.5us): global q gather + REDG, no smem ----
__device__ __forceinline__ void do_pair_g(
    float x, float y, float z, int i, int j,
    const float* __restrict__ q, float frcut, float cut2)
{
    float d2 = fmaf(x, x, fmaf(y, y, z * z));
    if (d2 <= cut2) {
        float qj = __ldg(&q[j]);
        float d = sqrtf(d2);
        float fr = __fdividef(erfcf(SQA * d), d) - frcut;
        atomicAdd(&g_yatom[i], qj * fr);
    }
}

__global__ __launch_bounds__(RTF) void real_kernel_g(
    const float* __restrict__ Rij,
    const int* __restrict__ idx_i, const int* __restrict__ idx_j,
    const float* __restrict__ q, int npairs)
{
    int tid = threadIdx.x;
    const float frcut = erfcf(SQA * CUTOFF) / CUTOFF;
    const float cut2 = CUTOFF * CUTOFF;

    int nquad = npairs >> 2;
    const float4* r4 = (const float4*)Rij;
    const int4*   i4 = (const int4*)idx_i;
    const int4*   j4 = (const int4*)idx_j;

    for (int qd = blockIdx.x * RTF + tid; qd < nquad; qd += RBF * RTF) {
        float4 A = r4[3 * qd], B = r4[3 * qd + 1], C = r4[3 * qd + 2];
        int4 ii = i4[qd];
        int4 jj = j4[qd];
        do_pair_g(A.x, A.y, A.z, ii.x, jj.x, q, frcut, cut2);
        do_pair_g(A.w, B.x, B.y, ii.y, jj.y, q, frcut, cut2);
        do_pair_g(B.z, B.w, C.x, ii.z, jj.z, q, frcut, cut2);
        do_pair_g(C.y, C.z, C.w, ii.w, jj.w, q, frcut, cut2);
    }
    int rem = npairs - (nquad << 2);
    if (blockIdx.x == 0 && tid < rem) {
        int p = (nquad << 2) + tid;
        do_pair_g(Rij[3 * p], Rij[3 * p + 1], Rij[3 * p + 2],
                  idx_i[p], idx_j[p], q, frcut, cut2);
    }
}

// =====================================================================
// Fold: y_mol = 0.5*KE * sum_a q[a] * g_yatom[a] over molecule range.
// =====================================================================
__global__ __launch_bounds__(256) void fold_kernel(
    const float* __restrict__ q, float* __restrict__ out)
{
    __shared__ float red[8];
    int m = blockIdx.x;
    int tid = threadIdx.x;
    int s0 = g_start[m], s1 = g_start[m + 1];
    float s = 0.0f;
    for (int a = s0 + tid; a < s1; a += 256) s += q[a] * g_yatom[a];
    #pragma unroll
    for (int o = 16; o; o >>= 1) s += __shfl_down_sync(0xffffffffu, s, o);
    int wid = tid >> 5, lid = tid & 31;
    if (lid == 0) red[wid] = s;
    __syncthreads();
    if (wid == 0) {
        s = (lid < 8) ? red[lid] : 0.0f;
        #pragma unroll
        for (int o = 4; o; o >>= 1) s += __shfl_down_sync(0xffffffffu, s, o);
        if (lid == 0) atomicAdd(&out[m], 0.5f * KE * s);
    }
}

// =====================================================================
// Reciprocal space (sliced structure factor): block = (mol, k-chunk,
// atom-slice); thread = one half-space k; +-k symmetry => x2 weight.
// =====================================================================
#define RT 256

__device__ __forceinline__ float block_sum(float v, float* sh)
{
    #pragma unroll
    for (int o = 16; o; o >>= 1) v += __shfl_down_sync(0xffffffffu, v, o);
    int wid = threadIdx.x >> 5, lid = threadIdx.x & 31;
    if (lid == 0) sh[wid] = v;
    __syncthreads();
    if (wid == 0) {
        v = (lid < (RT >> 5)) ? sh[lid] : 0.0f;
        #pragma unroll
        for (int o = 4; o; o >>= 1) v += __shfl_down_sync(0xffffffffu, v, o);
    }
    return v;   // valid on thread 0
}

__device__ float2 g_sf[NMOL][MAXK];     // complex structure factor partials
__device__ float  g_qq[NMOL];           // per-molecule sum q^2 partials

__global__ __launch_bounds__(256) void sfzero_kernel(void)
{
    int i = blockIdx.x * 256 + threadIdx.x;
    if (i < NMOL * MAXK) ((float2*)g_sf)[i] = make_float2(0.f, 0.f);
    if (i < NMOL) g_qq[i] = 0.0f;
}

__global__ __launch_bounds__(RT) void recip_sf_kernel(
    const float* __restrict__ R, const float* __restrict__ q,
    const float* __restrict__ kvecs)
{
    int m = blockIdx.x;
    int tid = threadIdx.x;
    int hk = blockIdx.y * RT + tid;
    int z  = blockIdx.z;

    float kvx = 0.f, kvy = 0.f, kvz = 0.f;
    if (hk < g_nhalf) {
        int k = g_halfk[hk];
        float gx = kvecs[3 * k], gy = kvecs[3 * k + 1], gz = kvecs[3 * k + 2];
        const float* B = g_recip[m];
        kvx = gx * B[0] + gy * B[3] + gz * B[6];
        kvy = gx * B[1] + gy * B[4] + gz * B[7];
        kvz = gx * B[2] + gy * B[5] + gz * B[8];
    }

    int m0 = g_start[m], m1 = g_start[m + 1];
    int len = m1 - m0;
    int per = (len + BZ - 1) / BZ;
    int s0 = m0 + z * per;
    int s1 = min(m1, s0 + per);

    __shared__ float4 tile[RT];
    __shared__ float red[RT >> 5];

    float cr = 0.f, ci = 0.f, qq = 0.f;
    for (int base = s0; base < s1; base += RT) {
        int a = base + tid;
        if (a < s1) {
            float qa = q[a];
            tile[tid] = make_float4(R[3 * a], R[3 * a + 1], R[3 * a + 2], qa);
            qq += qa * qa;
        }
        __syncthreads();
        int cnt = min(RT, s1 - base);
        #pragma unroll 4
        for (int t = 0; t < cnt; t++) {
            float4 v = tile[t];
            float kdp = kvx * v.x + kvy * v.y + kvz * v.z;
            float s, c;
            __sincosf(kdp, &s, &c);
            cr = fmaf(v.w, c, cr);
            ci = fmaf(v.w, s, ci);
        }
        __syncthreads();
    }

    if (hk < g_nhalf) {
        atomicAdd(&g_sf[m][hk].x, cr);
        atomicAdd(&g_sf[m][hk].y, ci);
    }
    if (blockIdx.y == 0) {
        float qqs = block_sum(qq, red);
        if (tid == 0) atomicAdd(&g_qq[m], qqs);
    }
}

__global__ __launch_bounds__(RT) void recip_epi_kernel(
    const float* __restrict__ kvecs, float* __restrict__ out)
{
    __shared__ float red[RT >> 5];
    int m = blockIdx.x;
    int tid = threadIdx.x;

    float acc = 0.f;
    for (int hk = tid; hk < g_nhalf; hk += RT) {
        int k = g_halfk[hk];
        float gx = kvecs[3 * k], gy = kvecs[3 * k + 1], gz = kvecs[3 * k + 2];
        const float* B = g_recip[m];
        float kvx = gx * B[0] + gy * B[3] + gz * B[6];
        float kvy = gx * B[1] + gy * B[4] + gz * B[7];
        float kvz = gx * B[2] + gy * B[5] + gz * B[8];
        float ksq = kvx * kvx + kvy * kvy + kvz * kvz;
        float w = 2.0f * expf(-0.25f * ksq / ALPHA) / ksq;   // x2: +-k symmetry
        float2 sf = g_sf[m][hk];
        acc = fmaf((sf.x * sf.x + sf.y * sf.y), w, acc);
    }
    acc = block_sum(acc, red);
    if (tid == 0) {
        float v = KE * (g_pref[m] * acc
                        - sqrtf(ALPHA / 3.14159265358979f) * g_qq[m]);
        atomicAdd(&out[m], v);
    }
}

// =====================================================================
extern "C" void kernel_launch(void* const* d_in, const int* in_sizes, int n_in,
                              void* d_out, int out_size)
{
    const float* q     = (const float*)d_in[0];      // partial_charges [A,1]
    const float* Rij   = (const float*)d_in[1];      // [P,3]
    const float* R     = (const float*)d_in[2];      // [A,3]
    const float* cell  = (const float*)d_in[3];      // [M,3,3]
    const float* kvecs = (const float*)d_in[4];      // [K,3]
    const int*   idx_m = (const int*)d_in[5];        // [A] int32
    const int*   idx_i = (const int*)d_in[6];        // [P] int32
    const int*   idx_j = (const int*)d_in[7];        // [P] int32
    float* out = (float*)d_out;

    int natoms = in_sizes[0];
    int npairs = in_sizes[1] / 3;
    int nk     = in_sizes[4] / 3;
    int nmol   = in_sizes[3] / 9;

    if (natoms > MAXA) natoms = MAXA;   // problem-fixed sizes; safety clamp

    int hs = (natoms + 1) >> 1;
    size_t smem_real = (size_t)hs * sizeof(float);   // 200 KB for natoms=100000

    int sblocks = (natoms + 255) / 256;
    if (sblocks < 1) sblocks = 1;

    int nhalf_max = (nk + 1) / 2;
    int gy = (nhalf_max + RT - 1) / RT;

    // One-time host resources for the capture-legal fork/join pattern.
    static cudaStream_t s2 = nullptr;
    static cudaEvent_t  e1 = nullptr, e2 = nullptr, eS = nullptr;
    static bool init_ok = false;
    static bool smem_ok = false;
    static bool init_tried = false;
    if (!init_tried) {
        init_tried = true;
        smem_ok = (cudaFuncSetAttribute(real_kernel,
                       cudaFuncAttributeMaxDynamicSharedMemorySize,
                       (int)smem_real) == cudaSuccess);
        init_ok = (cudaStreamCreateWithFlags(&s2, cudaStreamNonBlocking) == cudaSuccess) &&
                  (cudaEventCreateWithFlags(&e1, cudaEventDisableTiming) == cudaSuccess) &&
                  (cudaEventCreateWithFlags(&e2, cudaEventDisableTiming) == cudaSuccess) &&
                  (cudaEventCreateWithFlags(&eS, cudaEventDisableTiming) == cudaSuccess);
    }

    int sfblocks = (NMOL * MAXK + 255) / 256;

    if (init_ok) {
        // fork
        cudaEventRecord(e1, 0);
        cudaStreamWaitEvent(s2, e1, 0);
        // s2: setup -> sfzero -> sliced structure factor -> epilogue
        setup_kernel<<<sblocks, 256, 0, s2>>>(cell, kvecs, idx_m, natoms, nk, out);
        sfzero_kernel<<<sfblocks, 256, 0, s2>>>();
        cudaEventRecord(eS, s2);
        {
            dim3 grid(nmol, gy, BZ);
            recip_sf_kernel<<<grid, RT, 0, s2>>>(R, q, kvecs);
            recip_epi_kernel<<<nmol, RT, 0, s2>>>(kvecs, out);
        }
        // stream 0: zero -> real -> (after setup publishes g_start) fold
        zero_kernel<<<sblocks, 256>>>(natoms);
        if (smem_ok)
            real_kernel<<<RB, RTH, smem_real>>>(Rij, idx_i, idx_j, q, npairs, natoms);
        else
            real_kernel_g<<<RBF, RTF>>>(Rij, idx_i, idx_j, q, npairs);
        cudaStreamWaitEvent(0, eS, 0);
        fold_kernel<<<NMOL, 256>>>(q, out);
        // join
        cudaEventRecord(e2, s2);
        cudaStreamWaitEvent(0, e2, 0);
    } else {
        setup_kernel<<<sblocks, 256>>>(cell, kvecs, idx_m, natoms, nk, out);
        zero_kernel<<<sblocks, 256>>>(natoms);
        if (smem_ok)
            real_kernel<<<RB, RTH, smem_real>>>(Rij, idx_i, idx_j, q, npairs, natoms);
        else
            real_kernel_g<<<RBF, RTF>>>(Rij, idx_i, idx_j, q, npairs);
        fold_kernel<<<NMOL, 256>>>(q, out);
        sfzero_kernel<<<sfblocks, 256>>>();
        dim3 grid(nmol, gy, BZ);
        recip_sf_kernel<<<grid, RT>>>(R, q, kvecs);
        recip_epi_kernel<<<nmol, RT>>>(kvecs, out);
    }
}